// round 1
// baseline (speedup 1.0000x reference)
#include <cuda_runtime.h>
#include <math.h>

#define BS 8
#define F 16
#define NI 24
#define L 16384          // H*W = 128*128
#define CHUNKS1 32       // blocks per batch for sums kernel
#define CHUNKS3 32       // blocks per batch for var kernel

// ---------------- scratch (no allocations allowed) ----------------
__device__ float g_sums[BS][NI][F];
__device__ float g_counts[BS][NI];
__device__ float g_means[BS][NI][F];
__device__ float g_varnum[BS];
__device__ float g_varden[BS];
__device__ float g_hinge[BS];
__device__ float g_reg[BS];

// ---------------- K0: zero accumulators ----------------
__global__ void k_zero() {
    int tid = threadIdx.x;
    for (int i = tid; i < BS * NI * F; i += blockDim.x)
        ((float*)g_sums)[i] = 0.f;
    for (int i = tid; i < BS * NI; i += blockDim.x)
        ((float*)g_counts)[i] = 0.f;
    if (tid < BS) g_varnum[tid] = 0.f;
}

// ---------------- K1: per-batch sums[i][f] and counts[i] ----------------
// Warp handles 32-pixel groups: target -> ballot bitmasks (register-replicated),
// input transposed via padded shared tile, lanes = (f, pixel-half).
__global__ void __launch_bounds__(256) k_sums(const float* __restrict__ inp,
                                              const int* __restrict__ tgt) {
    const int b = blockIdx.y;
    const int chunk = blockIdx.x;                 // 0..CHUNKS1-1
    const int warp = threadIdx.x >> 5;            // 0..7
    const int lane = threadIdx.x & 31;
    const int f = lane & 15;
    const int half = lane >> 4;                   // 0: pixels 0-15, 1: 16-31
    const int CPIX = L / CHUNKS1;                 // 512
    const int NGROUPS = CPIX / 32;                // 16

    __shared__ float sh[8][32 * 17];              // per-warp [pix][f], pad 17

    float acc[NI];
#pragma unroll
    for (int i = 0; i < NI; i++) acc[i] = 0.f;
    float mycnt = 0.f;                            // lane i holds count for instance i

    for (int g = warp; g < NGROUPS; g += 8) {
        const int l0 = chunk * CPIX + g * 32;

        // --- build 32-pixel occupancy masks for all 24 instances ---
        unsigned m[NI];
        const int* tb = tgt + ((size_t)b * NI) * L + l0 + lane;
#pragma unroll
        for (int i = 0; i < NI; i++) {
            int t = tb[(size_t)i * L];
            unsigned mi = __ballot_sync(0xffffffffu, t != 0);
            m[i] = mi;
            if (lane == i) mycnt += (float)__popc(mi);
        }

        // --- transpose 32x16 input tile into shared ---
        const float* ib = inp + ((size_t)b * F) * L + l0 + lane;
        float* tile = &sh[warp][0];
#pragma unroll
        for (int ff = 0; ff < F; ff++)
            tile[lane * 17 + ff] = ib[(size_t)ff * L];
        __syncwarp();

        // --- accumulate: lane covers fixed f, its 16 pixels ---
#pragma unroll
        for (int k = 0; k < 16; k++) {
            const int pix = half * 16 + k;
            const float p = tile[pix * 17 + f];
            const unsigned bit = 1u << pix;
#pragma unroll
            for (int i = 0; i < NI; i++)
                if (m[i] & bit) acc[i] += p;
        }
        __syncwarp();
    }

    // combine the two pixel-halves per f, then flush
#pragma unroll
    for (int i = 0; i < NI; i++) {
        float v = acc[i] + __shfl_down_sync(0xffffffffu, acc[i], 16);
        if (lane < 16) atomicAdd(&g_sums[b][i][f], v);
    }
    if (lane < NI) atomicAdd(&g_counts[b][lane], mycnt);
}

// ---------------- K2: means, var_den, hinge(dist), reg ----------------
__global__ void k_stats(const int* __restrict__ nobj_arr) {
    __shared__ float sh_hinge[BS], sh_reg[BS], sh_varden[BS];
    const int tid = threadIdx.x;
    if (tid < BS) { sh_hinge[tid] = 0.f; sh_reg[tid] = 0.f; sh_varden[tid] = 0.f; }
    __syncthreads();

    // means
    for (int idx = tid; idx < BS * NI * F; idx += blockDim.x) {
        int b = idx / (NI * F); int r = idx % (NI * F);
        int i = r / F; int f = r % F;
        int nb = nobj_arr[b];
        float mval = 0.f;
        if (i < nb) {
            float c = g_counts[b][i];
            mval = g_sums[b][i][f] / (c > 0.f ? c : 1.f);
        }
        g_means[b][i][f] = mval;
    }
    __syncthreads();

    // var_den + reg (per (b,i))
    for (int idx = tid; idx < BS * NI; idx += blockDim.x) {
        int b = idx / NI; int i = idx % NI;
        int nb = nobj_arr[b];
        if (i < nb) {
            atomicAdd(&sh_varden[b], g_counts[b][i]);
            float ss = 0.f;
#pragma unroll
            for (int f = 0; f < F; f++) { float m = g_means[b][i][f]; ss += m * m; }
            atomicAdd(&sh_reg[b], ss > 0.f ? sqrtf(ss) : 0.f);
        }
    }

    // pairwise hinge (per (b,i,j))
    for (int idx = tid; idx < BS * NI * NI; idx += blockDim.x) {
        int b = idx / (NI * NI); int r = idx % (NI * NI);
        int i = r / NI; int j = r % NI;
        int nb = nobj_arr[b];
        if (i < nb && j < nb && i != j) {
            float ss = 0.f;
#pragma unroll
            for (int f = 0; f < F; f++) {
                float d = g_means[b][i][f] - g_means[b][j][f];
                ss += d * d;
            }
            float dn = ss > 0.f ? sqrtf(ss) : 0.f;
            float h = fmaxf(3.0f - dn, 0.f);   // margin = 2*DELTA_D = 3 for i!=j
            atomicAdd(&sh_hinge[b], h * h);
        }
    }
    __syncthreads();
    if (tid < BS) {
        g_varden[tid] = sh_varden[tid];
        g_hinge[tid]  = sh_hinge[tid];
        g_reg[tid]    = sh_reg[tid];
    }
}

// ---------------- K3: var_num ----------------
__global__ void __launch_bounds__(256) k_var(const float* __restrict__ inp,
                                             const int* __restrict__ tgt,
                                             const int* __restrict__ nobj_arr) {
    const int b = blockIdx.y;
    const int chunk = blockIdx.x;                 // 0..CHUNKS3-1
    const int tid = threadIdx.x;
    const int PIX = L / CHUNKS3;                  // 512

    __shared__ float msh[NI][F];
    __shared__ float red[8];
    for (int i = tid; i < NI * F; i += blockDim.x)
        ((float*)msh)[i] = ((const float*)g_means)[b * NI * F + i];
    __syncthreads();

    const int nb = nobj_arr[b];
    float local = 0.f;

    for (int pp = tid; pp < PIX; pp += blockDim.x) {
        const int l = chunk * PIX + pp;
        const float* ib = inp + (size_t)b * F * L + l;
        float p[F];
#pragma unroll
        for (int f = 0; f < F; f++) p[f] = ib[(size_t)f * L];

        const int* tb = tgt + (size_t)b * NI * L + l;
        for (int i = 0; i < nb; i++) {
            int t = tb[(size_t)i * L];
            if (t) {
                float ss = 0.f;
#pragma unroll
                for (int f = 0; f < F; f++) {
                    float d = p[f] - msh[i][f];
                    ss += d * d;
                }
                float h = fmaxf(sqrtf(ss) - 0.5f, 0.f);
                local += h * h;
            }
        }
    }

    // block reduce -> atomic per batch
#pragma unroll
    for (int o = 16; o > 0; o >>= 1)
        local += __shfl_down_sync(0xffffffffu, local, o);
    if ((tid & 31) == 0) red[tid >> 5] = local;
    __syncthreads();
    if (tid < 8) {
        float v = red[tid];
#pragma unroll
        for (int o = 4; o > 0; o >>= 1)
            v += __shfl_down_sync(0xffu, v, o);
        if (tid == 0) atomicAdd(&g_varnum[b], v);
    }
}

// ---------------- K4: finalize ----------------
__global__ void k_final(const int* __restrict__ nobj_arr, float* __restrict__ out) {
    if (threadIdx.x == 0) {
        float var_t = 0.f, dist_t = 0.f, reg_t = 0.f;
        for (int b = 0; b < BS; b++) {
            var_t += g_varnum[b] / g_varden[b];
            float nf = (float)nobj_arr[b];
            float denom = nf > 1.f ? nf * (nf - 1.f) : 1.f;
            dist_t += (nf > 1.f) ? g_hinge[b] / denom : 0.f;
            reg_t += g_reg[b] / nf;
        }
        out[0] = var_t / BS + dist_t / BS + 0.001f * (reg_t / BS);
    }
}

// ---------------- launch ----------------
extern "C" void kernel_launch(void* const* d_in, const int* in_sizes, int n_in,
                              void* d_out, int out_size) {
    const float* inp  = (const float*)d_in[0];   // (8,16,128,128) f32
    const int*   tgt  = (const int*)d_in[1];     // (8,24,128,128) i32
    const int*   nobj = (const int*)d_in[2];     // (8,1) i32
    (void)in_sizes; (void)n_in; (void)out_size;

    k_zero<<<1, 256>>>();
    dim3 g1(CHUNKS1, BS);
    k_sums<<<g1, 256>>>(inp, tgt);
    k_stats<<<1, 256>>>(nobj);
    dim3 g3(CHUNKS3, BS);
    k_var<<<g3, 256>>>(inp, tgt, nobj);
    k_final<<<1, 32>>>(nobj, (float*)d_out);
}

// round 2
// speedup vs baseline: 1.1704x; 1.1704x over previous
#include <cuda_runtime.h>
#include <math.h>

#define BS 8
#define F 16
#define NI 24
#define L 16384            // H*W = 128*128
#define NGRP (L / 32)      // 512 groups of 32 pixels per batch

// ---------------- scratch (no allocations allowed) ----------------
__device__ float    g_sums[BS][NI][F];
__device__ float    g_counts[BS][NI];
__device__ float    g_means[BS][NI][F];
__device__ unsigned g_masks[BS][NGRP][NI];
__device__ float    g_varnum[BS];
__device__ float    g_varden[BS];
__device__ float    g_hinge[BS];
__device__ float    g_reg[BS];

// ---------------- K0: zero accumulators ----------------
__global__ void k_zero() {
    int tid = threadIdx.x;
    for (int i = tid; i < BS * NI * F; i += blockDim.x)
        ((float*)g_sums)[i] = 0.f;
    for (int i = tid; i < BS * NI; i += blockDim.x)
        ((float*)g_counts)[i] = 0.f;
    if (tid < BS) g_varnum[tid] = 0.f;
}

// ---------------- K1: sums[i][f], counts[i], persist masks ----------------
// One warp per 32-pixel group. grid = (NGRP/8, BS), 256 threads.
__global__ void __launch_bounds__(256) k_sums(const float* __restrict__ inp,
                                              const int* __restrict__ tgt) {
    const int b    = blockIdx.y;
    const int warp = threadIdx.x >> 5;
    const int lane = threadIdx.x & 31;
    const int grp  = blockIdx.x * 8 + warp;       // 0..NGRP-1
    const int l0   = grp * 32;
    const int f    = lane & 15;
    const int half = lane >> 4;

    __shared__ float sh[8][32 * 17];              // per-warp transpose tile
    __shared__ float ssum[NI][F];                 // block-stage accumulators
    __shared__ float scnt[NI];

    for (int i = threadIdx.x; i < NI * F; i += 256) ((float*)ssum)[i] = 0.f;
    if (threadIdx.x < NI) scnt[threadIdx.x] = 0.f;
    __syncthreads();

    // --- occupancy masks for all 24 instances (register-replicated) ---
    unsigned m[NI];
    unsigned my_m = 0;
    const int* tb = tgt + ((size_t)b * NI) * L + l0 + lane;
#pragma unroll
    for (int i = 0; i < NI; i++) {
        int t = tb[(size_t)i * L];
        unsigned mi = __ballot_sync(0xffffffffu, t != 0);
        m[i] = mi;
        if (lane == i) my_m = mi;
    }
    if (lane < NI) g_masks[b][grp][lane] = my_m;

    // --- transpose 32x16 input tile ---
    const float* ib = inp + ((size_t)b * F) * L + l0 + lane;
    float* tile = &sh[warp][0];
#pragma unroll
    for (int ff = 0; ff < F; ff++)
        tile[lane * 17 + ff] = ib[(size_t)ff * L];
    __syncwarp();

    // --- accumulate: lane = (f, pixel-half) ---
    float acc[NI];
#pragma unroll
    for (int i = 0; i < NI; i++) acc[i] = 0.f;
#pragma unroll
    for (int k = 0; k < 16; k++) {
        const int pix = half * 16 + k;
        const float p = tile[pix * 17 + f];
        const unsigned bit = 1u << pix;
#pragma unroll
        for (int i = 0; i < NI; i++)
            if (m[i] & bit) acc[i] += p;
    }

    // --- warp halves -> shared atomics (block stage) ---
#pragma unroll
    for (int i = 0; i < NI; i++) {
        float v = acc[i] + __shfl_down_sync(0xffffffffu, acc[i], 16);
        if (lane < 16) atomicAdd(&ssum[i][f], v);
    }
    if (lane < NI) atomicAdd(&scnt[lane], (float)__popc(my_m));
    __syncthreads();

    // --- one global atomic per (i,f) per block ---
    for (int i = threadIdx.x; i < NI * F; i += 256)
        atomicAdd(&((float*)g_sums)[b * NI * F + i], ((float*)ssum)[i]);
    if (threadIdx.x < NI)
        atomicAdd(&g_counts[b][threadIdx.x], scnt[threadIdx.x]);
}

// ---------------- K2: means, var_den, hinge(dist), reg ----------------
__global__ void k_stats(const int* __restrict__ nobj_arr) {
    __shared__ float sh_hinge[BS], sh_reg[BS], sh_varden[BS];
    const int tid = threadIdx.x;
    if (tid < BS) { sh_hinge[tid] = 0.f; sh_reg[tid] = 0.f; sh_varden[tid] = 0.f; }
    __syncthreads();

    for (int idx = tid; idx < BS * NI * F; idx += blockDim.x) {
        int b = idx / (NI * F); int r = idx % (NI * F);
        int i = r / F; int f = r % F;
        int nb = nobj_arr[b];
        float mval = 0.f;
        if (i < nb) {
            float c = g_counts[b][i];
            mval = g_sums[b][i][f] / (c > 0.f ? c : 1.f);
        }
        g_means[b][i][f] = mval;
    }
    __syncthreads();

    for (int idx = tid; idx < BS * NI; idx += blockDim.x) {
        int b = idx / NI; int i = idx % NI;
        int nb = nobj_arr[b];
        if (i < nb) {
            atomicAdd(&sh_varden[b], g_counts[b][i]);
            float ss = 0.f;
#pragma unroll
            for (int f = 0; f < F; f++) { float m = g_means[b][i][f]; ss += m * m; }
            atomicAdd(&sh_reg[b], ss > 0.f ? sqrtf(ss) : 0.f);
        }
    }

    for (int idx = tid; idx < BS * NI * NI; idx += blockDim.x) {
        int b = idx / (NI * NI); int r = idx % (NI * NI);
        int i = r / NI; int j = r % NI;
        int nb = nobj_arr[b];
        if (i < nb && j < nb && i != j) {
            float ss = 0.f;
#pragma unroll
            for (int f = 0; f < F; f++) {
                float d = g_means[b][i][f] - g_means[b][j][f];
                ss += d * d;
            }
            float dn = ss > 0.f ? sqrtf(ss) : 0.f;
            float h = fmaxf(3.0f - dn, 0.f);   // margin = 2*DELTA_D
            atomicAdd(&sh_hinge[b], h * h);
        }
    }
    __syncthreads();
    if (tid < BS) {
        g_varden[tid] = sh_varden[tid];
        g_hinge[tid]  = sh_hinge[tid];
        g_reg[tid]    = sh_reg[tid];
    }
}

// ---------------- K3: var_num (mask-driven, 1 pixel / thread) ----------------
__global__ void __launch_bounds__(256) k_var(const float* __restrict__ inp,
                                             const int* __restrict__ nobj_arr) {
    const int b    = blockIdx.y;
    const int tid  = threadIdx.x;
    const int lane = tid & 31;
    const int warp = tid >> 5;
    const int l    = blockIdx.x * 256 + tid;      // pixel index
    const int grp  = blockIdx.x * 8 + warp;

    __shared__ float msh[NI][F];
    __shared__ float red[8];
    for (int i = tid; i < NI * F; i += 256)
        ((float*)msh)[i] = ((const float*)g_means)[b * NI * F + i];
    __syncthreads();

    // per-pixel feature vector (coalesced across lanes)
    const float* ib = inp + (size_t)b * F * L + l;
    float p[F];
#pragma unroll
    for (int f = 0; f < F; f++) p[f] = ib[(size_t)f * L];

    // this warp's instance masks (lane i holds mask for instance i)
    unsigned mw = 0;
    if (lane < NI) mw = g_masks[b][grp][lane];

    const int nb = nobj_arr[b];
    float local = 0.f;

    for (int i = 0; i < nb; i++) {
        unsigned mi = __shfl_sync(0xffffffffu, mw, i);
        if ((mi >> lane) & 1u) {
            float ss = 0.f;
#pragma unroll
            for (int f = 0; f < F; f++) {
                float d = p[f] - msh[i][f];
                ss += d * d;
            }
            if (ss > 0.25f) {                     // delta_v^2
                float h = sqrtf(ss) - 0.5f;
                local += h * h;
            }
        }
    }

#pragma unroll
    for (int o = 16; o > 0; o >>= 1)
        local += __shfl_down_sync(0xffffffffu, local, o);
    if (lane == 0) red[warp] = local;
    __syncthreads();
    if (tid < 8) {
        float v = red[tid];
#pragma unroll
        for (int o = 4; o > 0; o >>= 1)
            v += __shfl_down_sync(0xffu, v, o);
        if (tid == 0) atomicAdd(&g_varnum[b], v);
    }
}

// ---------------- K4: finalize ----------------
__global__ void k_final(const int* __restrict__ nobj_arr, float* __restrict__ out) {
    if (threadIdx.x == 0) {
        float var_t = 0.f, dist_t = 0.f, reg_t = 0.f;
        for (int b = 0; b < BS; b++) {
            var_t += g_varnum[b] / g_varden[b];
            float nf = (float)nobj_arr[b];
            float denom = nf > 1.f ? nf * (nf - 1.f) : 1.f;
            dist_t += (nf > 1.f) ? g_hinge[b] / denom : 0.f;
            reg_t += g_reg[b] / nf;
        }
        out[0] = var_t / BS + dist_t / BS + 0.001f * (reg_t / BS);
    }
}

// ---------------- launch ----------------
extern "C" void kernel_launch(void* const* d_in, const int* in_sizes, int n_in,
                              void* d_out, int out_size) {
    const float* inp  = (const float*)d_in[0];   // (8,16,128,128) f32
    const int*   tgt  = (const int*)d_in[1];     // (8,24,128,128) i32
    const int*   nobj = (const int*)d_in[2];     // (8,1) i32
    (void)in_sizes; (void)n_in; (void)out_size;

    k_zero<<<1, 256>>>();
    dim3 g1(NGRP / 8, BS);                       // 64 x 8 = 512 blocks
    k_sums<<<g1, 256>>>(inp, tgt);
    k_stats<<<1, 256>>>(nobj);
    dim3 g3(L / 256, BS);                        // 64 x 8 = 512 blocks
    k_var<<<g3, 256>>>(inp, nobj);
    k_final<<<1, 32>>>(nobj, (float*)d_out);
}

// round 3
// speedup vs baseline: 1.1752x; 1.0041x over previous
#include <cuda_runtime.h>
#include <math.h>

#define BS 8
#define F 16
#define NI 24
#define L 16384            // H*W
#define NGRP (L / 32)      // 512 pixel-groups per batch
#define BLKX 64            // grid.x for both big kernels (x8 warps = 512 groups)

// ---------------- scratch (no allocations allowed) ----------------
__device__ float    g_sums[BS][NI][F];
__device__ float    g_counts[BS][NI];
__device__ float    g_means[BS][NI][F];
__device__ unsigned g_masks[BS][NGRP][NI];
__device__ float    g_varnum[BS];
__device__ float    g_varden[BS];
__device__ float    g_hinge[BS];
__device__ float    g_reg[BS];
__device__ unsigned g_cnt1;
__device__ unsigned g_cnt2;

// ---------------- K0: zero accumulators + counters ----------------
__global__ void k_zero() {
    int tid = threadIdx.x;
    for (int i = tid; i < BS * NI * F; i += blockDim.x)
        ((float*)g_sums)[i] = 0.f;
    for (int i = tid; i < BS * NI; i += blockDim.x)
        ((float*)g_counts)[i] = 0.f;
    if (tid < BS) g_varnum[tid] = 0.f;
    if (tid == 0) { g_cnt1 = 0u; g_cnt2 = 0u; }
}

// ---------------- K1: sums/counts/masks + (last block) stats ----------------
// One warp per 32-pixel group. grid = (BLKX, BS), 256 threads.
__global__ void __launch_bounds__(256) k_sums(const float* __restrict__ inp,
                                              const int* __restrict__ tgt,
                                              const int* __restrict__ nobj) {
    const int b    = blockIdx.y;
    const int warp = threadIdx.x >> 5;
    const int lane = threadIdx.x & 31;
    const int grp  = blockIdx.x * 8 + warp;       // 0..NGRP-1
    const int l0   = grp * 32;
    const int f    = lane & 15;
    const int half = lane >> 4;
    const int nb   = __ldg(nobj + b);

    __shared__ float sh_w[8][NI * F];
    __shared__ float sh_c[8][NI];
    __shared__ bool  sh_last;

    // --- 16 contiguous pixels of feature row f (4x LDG.128, fully coalesced) ---
    const float* ip = inp + ((size_t)b * F + f) * L + l0 + half * 16;
    float4 v0 = *(const float4*)(ip + 0);
    float4 v1 = *(const float4*)(ip + 4);
    float4 v2 = *(const float4*)(ip + 8);
    float4 v3 = *(const float4*)(ip + 12);
    float preg[16] = {v0.x, v0.y, v0.z, v0.w, v1.x, v1.y, v1.z, v1.w,
                      v2.x, v2.y, v2.z, v2.w, v3.x, v3.y, v3.z, v3.w};

    // --- batched target loads (lane = pixel), only valid instances ---
    const int* tb = tgt + ((size_t)b * NI) * L + l0 + lane;
    int tval[NI];
#pragma unroll
    for (int i = 0; i < NI; i++)
        tval[i] = (i < nb) ? tb[(size_t)i * L] : 0;

    // --- per-instance: ballot -> mask persist + masked accumulate ---
#pragma unroll
    for (int i = 0; i < NI; i++) {
        if (i >= nb) break;                        // nb warp-uniform
        unsigned mi = __ballot_sync(0xffffffffu, tval[i] != 0);
        if (lane == 0) {
            g_masks[b][grp][i] = mi;
            sh_c[warp][i] = (float)__popc(mi);
        }
        unsigned sub = mi >> (half * 16);
        float a = 0.f;
#pragma unroll
        for (int k = 0; k < 16; k++)
            if ((sub >> k) & 1u) a += preg[k];
        a += __shfl_down_sync(0xffffffffu, a, 16);
        if (lane < 16) sh_w[warp][i * 16 + lane] = a;
    }
    __syncthreads();

    // --- block tree-reduce -> one global atomic per (i,f) ---
    for (int idx = threadIdx.x; idx < NI * F; idx += 256) {
        int i = idx >> 4;
        if (i < nb) {
            float s = 0.f;
#pragma unroll
            for (int w = 0; w < 8; w++) s += sh_w[w][idx];
            atomicAdd(&((float*)g_sums)[b * NI * F + idx], s);
        }
    }
    if (threadIdx.x < NI && threadIdx.x < nb) {
        float s = 0.f;
#pragma unroll
        for (int w = 0; w < 8; w++) s += sh_c[w][threadIdx.x];
        atomicAdd(&g_counts[b][threadIdx.x], s);
    }

    // --- last block computes means / varden / hinge / reg for ALL batches ---
    __threadfence();
    if (threadIdx.x == 0)
        sh_last = (atomicAdd(&g_cnt1, 1u) == (unsigned)(BLKX * BS) - 1u);
    __syncthreads();
    if (!sh_last) return;

    const int tid = threadIdx.x;
    __shared__ float sh_h[BS], sh_r[BS], sh_v[BS];
    if (tid < BS) { sh_h[tid] = 0.f; sh_r[tid] = 0.f; sh_v[tid] = 0.f; }
    __syncthreads();

    // means
    for (int idx = tid; idx < BS * NI * F; idx += 256) {
        int bb = idx / (NI * F);
        int i  = (idx % (NI * F)) >> 4;
        int nbb = nobj[bb];
        float mval = 0.f;
        if (i < nbb) {
            float c = g_counts[bb][i];
            mval = ((float*)g_sums)[idx] / (c > 0.f ? c : 1.f);
        }
        ((float*)g_means)[idx] = mval;
    }
    __syncthreads();

    // varden + reg
    for (int idx = tid; idx < BS * NI; idx += 256) {
        int bb = idx / NI, i = idx % NI;
        if (i < nobj[bb]) {
            atomicAdd(&sh_v[bb], g_counts[bb][i]);
            float ss = 0.f;
#pragma unroll
            for (int ff = 0; ff < F; ff++) {
                float m = g_means[bb][i][ff];
                ss += m * m;
            }
            atomicAdd(&sh_r[bb], ss > 0.f ? sqrtf(ss) : 0.f);
        }
    }
    // pairwise hinge
    for (int idx = tid; idx < BS * NI * NI; idx += 256) {
        int bb = idx / (NI * NI);
        int r = idx % (NI * NI);
        int i = r / NI, j = r % NI;
        int nbb = nobj[bb];
        if (i < nbb && j < nbb && i != j) {
            float ss = 0.f;
#pragma unroll
            for (int ff = 0; ff < F; ff++) {
                float d = g_means[bb][i][ff] - g_means[bb][j][ff];
                ss += d * d;
            }
            float dn = ss > 0.f ? sqrtf(ss) : 0.f;
            float h = fmaxf(3.0f - dn, 0.f);      // margin = 2*delta_d
            atomicAdd(&sh_h[bb], h * h);
        }
    }
    __syncthreads();
    if (tid < BS) {
        g_varden[tid] = sh_v[tid];
        g_hinge[tid]  = sh_h[tid];
        g_reg[tid]    = sh_r[tid];
    }
}

// ---------------- K2: var_num (mask-driven, f32x2 math) + (last block) final ----
__global__ void __launch_bounds__(256) k_var(const float* __restrict__ inp,
                                             const int* __restrict__ nobj,
                                             float* __restrict__ out) {
    const int b    = blockIdx.y;
    const int tid  = threadIdx.x;
    const int lane = tid & 31;
    const int warp = tid >> 5;
    const int l    = blockIdx.x * 256 + tid;
    const int grp  = blockIdx.x * 8 + warp;
    const int nb   = __ldg(nobj + b);

    __shared__ ulonglong2 msh2[NI * 4];   // negated means, 4x16B per instance
    __shared__ float red[8];
    __shared__ bool sh_last;

    for (int idx = tid; idx < NI * F; idx += 256)
        ((float*)msh2)[idx] = -((const float*)g_means)[b * NI * F + idx];
    __syncthreads();

    // per-pixel feature vector packed into 8 f32x2 regs
    const float* ib = inp + (size_t)b * F * L + l;
    unsigned long long p2[8];
#pragma unroll
    for (int j = 0; j < 8; j++) {
        float lo = ib[(size_t)(2 * j) * L];
        float hi = ib[(size_t)(2 * j + 1) * L];
        asm("mov.b64 %0,{%1,%2};" : "=l"(p2[j]) : "f"(lo), "f"(hi));
    }

    unsigned mw = (lane < NI) ? g_masks[b][grp][lane] : 0u;
    float local = 0.f;

#pragma unroll
    for (int i = 0; i < NI; i++) {
        if (i >= nb) break;
        unsigned mi = __shfl_sync(0xffffffffu, mw, i);
        if ((mi >> lane) & 1u) {
            unsigned long long ssa = 0ull, ssb = 0ull;  // bitwise 0 == (0.f,0.f)
#pragma unroll
            for (int q = 0; q < 4; q++) {
                ulonglong2 mv = msh2[i * 4 + q];
                unsigned long long d0, d1;
                asm("add.rn.f32x2 %0,%1,%2;" : "=l"(d0) : "l"(p2[2 * q]),     "l"(mv.x));
                asm("add.rn.f32x2 %0,%1,%2;" : "=l"(d1) : "l"(p2[2 * q + 1]), "l"(mv.y));
                asm("fma.rn.f32x2 %0,%1,%2,%3;" : "=l"(ssa) : "l"(d0), "l"(d0), "l"(ssa));
                asm("fma.rn.f32x2 %0,%1,%2,%3;" : "=l"(ssb) : "l"(d1), "l"(d1), "l"(ssb));
            }
            float alo, ahi, blo, bhi;
            asm("mov.b64 {%0,%1},%2;" : "=f"(alo), "=f"(ahi) : "l"(ssa));
            asm("mov.b64 {%0,%1},%2;" : "=f"(blo), "=f"(bhi) : "l"(ssb));
            float ss = (alo + ahi) + (blo + bhi);
            if (ss > 0.25f) {                     // delta_v^2
                float h = sqrtf(ss) - 0.5f;
                local += h * h;
            }
        }
    }

    // block reduce -> atomic per batch
#pragma unroll
    for (int o = 16; o > 0; o >>= 1)
        local += __shfl_down_sync(0xffffffffu, local, o);
    if (lane == 0) red[warp] = local;
    __syncthreads();
    if (tid < 8) {
        float v = red[tid];
#pragma unroll
        for (int o = 4; o > 0; o >>= 1)
            v += __shfl_down_sync(0xffu, v, o);
        if (tid == 0) atomicAdd(&g_varnum[b], v);
    }

    // --- last block computes the final scalar ---
    __threadfence();
    if (tid == 0)
        sh_last = (atomicAdd(&g_cnt2, 1u) == (unsigned)(BLKX * BS) - 1u);
    __syncthreads();
    if (!sh_last) return;

    if (tid == 0) {
        float var_t = 0.f, dist_t = 0.f, reg_t = 0.f;
        for (int bb = 0; bb < BS; bb++) {
            var_t += g_varnum[bb] / g_varden[bb];
            float nf = (float)nobj[bb];
            float denom = nf > 1.f ? nf * (nf - 1.f) : 1.f;
            dist_t += (nf > 1.f) ? g_hinge[bb] / denom : 0.f;
            reg_t += g_reg[bb] / nf;
        }
        out[0] = var_t / BS + dist_t / BS + 0.001f * (reg_t / BS);
    }
}

// ---------------- launch ----------------
extern "C" void kernel_launch(void* const* d_in, const int* in_sizes, int n_in,
                              void* d_out, int out_size) {
    const float* inp  = (const float*)d_in[0];   // (8,16,128,128) f32
    const int*   tgt  = (const int*)d_in[1];     // (8,24,128,128) i32
    const int*   nobj = (const int*)d_in[2];     // (8,1) i32
    (void)in_sizes; (void)n_in; (void)out_size;

    k_zero<<<1, 256>>>();
    dim3 g(BLKX, BS);
    k_sums<<<g, 256>>>(inp, tgt, nobj);
    k_var<<<g, 256>>>(inp, nobj, (float*)d_out);
}